// round 14
// baseline (speedup 1.0000x reference)
#include <cuda_runtime.h>
#include <math.h>

#define HH 128
#define WW 128
#define HWSZ (HH*WW)
#define NFC 64
#define BB 4

// Scratch ping-pong buffers (no allocation allowed)
__device__ float g_bufA[BB*NFC*HWSZ];
__device__ float g_bufB[BB*NFC*HWSZ];

// Keeps the ncu window (0-based launch #3) on conv1 for comparable profiles.
__global__ void sched_warm_k() {}

// ---------------------------------------------------------------------------
// Tiled 3x3 conv, stride 1, pad 1. (R6/R13 measured-best config, unchanged)
// ---------------------------------------------------------------------------
__global__ __launch_bounds__(128) void conv3x3_k(
    const float* __restrict__ in0, const float* __restrict__ in1, int cin,
    const float* __restrict__ wgt, const float* __restrict__ bias,
    float* __restrict__ out, int cout, int mode,
    float* __restrict__ outOff, float* __restrict__ outMask)
{
    __shared__ float s_in[8][18][34];   // [ci][row 16+2][col 32+2]
    __shared__ float s_w[8][8][9];      // [oc][ci][k]

    const int tx = threadIdx.x;         // 0..7
    const int ty = threadIdx.y;         // 0..15
    const int tid = ty * 8 + tx;
    const int x0 = blockIdx.x * 32;
    const int y0 = blockIdx.y * 16;
    const int groups = (cout + 7) / 8;
    const int b = blockIdx.z / groups;
    const int ocBase = (blockIdx.z % groups) * 8;

    float acc[8][4];
#pragma unroll
    for (int o = 0; o < 8; o++)
#pragma unroll
        for (int p = 0; p < 4; p++) acc[o][p] = 0.f;

    for (int cb = 0; cb < cin; cb += 8) {
        __syncthreads();
        for (int idx = tid; idx < 8 * 612; idx += 128) {
            int ci = idx / 612;
            int rem = idx % 612;
            int r = rem / 34;
            int c = rem % 34;
            int gy = y0 + r - 1;
            int gx = x0 + c - 1;
            int ch = cb + ci;
            const float* src = in0;
            int chl = ch;
            if (ch >= 64) { src = in1; chl = ch - 64; }
            float v = 0.f;
            if (gy >= 0 && gy < HH && gx >= 0 && gx < WW)
                v = __ldg(&src[((b * 64 + chl) * HH + gy) * WW + gx]);
            (&s_in[0][0][0])[idx] = v;
        }
        for (int idx = tid; idx < 8 * 8 * 9; idx += 128) {
            int oc = idx / 72;
            int rem = idx % 72;
            int ci = rem / 9;
            int k = rem % 9;
            int gc = ocBase + oc;
            float v = 0.f;
            if (gc < cout) v = __ldg(&wgt[(gc * cin + cb + ci) * 9 + k]);
            (&s_w[0][0][0])[idx] = v;
        }
        __syncthreads();

#pragma unroll 2
        for (int ci = 0; ci < 8; ci++) {
            float v[3][6];
#pragma unroll
            for (int r = 0; r < 3; r++)
#pragma unroll
                for (int c = 0; c < 6; c++)
                    v[r][c] = s_in[ci][ty + r][tx * 4 + c];
#pragma unroll
            for (int oc = 0; oc < 8; oc++) {
#pragma unroll
                for (int kr = 0; kr < 3; kr++)
#pragma unroll
                    for (int kc = 0; kc < 3; kc++) {
                        float wv = s_w[oc][ci][kr * 3 + kc];
#pragma unroll
                        for (int p = 0; p < 4; p++)
                            acc[oc][p] = fmaf(v[kr][kc + p], wv, acc[oc][p]);
                    }
            }
        }
    }

    const int y = y0 + ty;
    const int xb = x0 + tx * 4;
#pragma unroll
    for (int oc = 0; oc < 8; oc++) {
        int gc = ocBase + oc;
        if (gc >= cout) continue;
        float bv = __ldg(&bias[gc]);
        float r[4];
#pragma unroll
        for (int p = 0; p < 4; p++) r[p] = acc[oc][p] + bv;
        if (mode == 0) {
#pragma unroll
            for (int p = 0; p < 4; p++) r[p] = (r[p] >= 0.f) ? r[p] : 0.1f * r[p];
            float4 v4 = make_float4(r[0], r[1], r[2], r[3]);
            *(float4*)&out[((b * cout + gc) * HH + y) * WW + xb] = v4;
        } else {
            if (gc < 18) {
#pragma unroll
                for (int p = 0; p < 4; p++) r[p] = 15.f * tanhf(r[p]);
                float4 v4 = make_float4(r[0], r[1], r[2], r[3]);
                *(float4*)&outOff[((b * 18 + gc) * HH + y) * WW + xb] = v4;
            } else {
#pragma unroll
                for (int p = 0; p < 4; p++) r[p] = 1.f / (1.f + expf(-r[p]));
                float4 v4 = make_float4(r[0], r[1], r[2], r[3]);
                *(float4*)&outMask[((b * 9 + (gc - 18)) * HH + y) * WW + xb] = v4;
            }
        }
    }
}

// ---------------------------------------------------------------------------
// DCNv2, all-register formulation.
// Block = 2 rows x 128 px = 256 threads. Thread = 1 px, ALL 64 oc (acc[64]).
// Bilinear tabs built once into smem (private per-thread entries).
// Per 4-ci chunk: weights double-buffered (prefetch overlaps GEMM),
// gather -> samp[36] REGISTERS (no s_samp, no second barrier),
// GEMM reads s_w via warp-broadcast LDS.128. One __syncthreads per chunk.
// smem 73728 B -> 2 blocks/SM.
// ---------------------------------------------------------------------------
__global__ __launch_bounds__(256, 2) void dcn_reg_k(
    const float* __restrict__ xin, const float* __restrict__ off,
    const float* __restrict__ msk, const float* __restrict__ wgt,
    const float* __restrict__ bias, float* __restrict__ out)
{
    extern __shared__ float sm[];
    float4*  s_tabw = (float4*)sm;                   // 9*256*16 = 36864 B
    ushort4* s_tabi = (ushort4*)(sm + 9216);         // 9*256*8  = 18432 B
    float*   s_w    = sm + 9216 + 4608;              // 2*36*64*4 = 18432 B

    const int tid  = threadIdx.x;      // 0..255
    const int b    = blockIdx.y;
    const int row0 = blockIdx.x * 2;
    const int lx   = tid & 127;
    const int y    = row0 + (tid >> 7);

    // ---- Phase A: bilinear tab for this thread's pixel, 9 taps
    {
        const int x = lx;
#pragma unroll
        for (int k = 0; k < 9; k++) {
            float oy = __ldg(&off[((b * 18 + 2 * k) * HH + y) * WW + x]);
            float ox = __ldg(&off[((b * 18 + 2 * k + 1) * HH + y) * WW + x]);
            float m  = __ldg(&msk[((b * 9 + k) * HH + y) * WW + x]);
            float py  = (float)(y + k / 3 - 1) + oy;
            float pxf = (float)(x + k % 3 - 1) + ox;
            float fy = floorf(py);
            float fx = floorf(pxf);
            float wy = py - fy;
            float wx = pxf - fx;
            int iy = (int)fy;
            int ix = (int)fx;
            bool vy0 = ((unsigned)iy) < 128u;
            bool vy1 = ((unsigned)(iy + 1)) < 128u;
            bool vx0 = ((unsigned)ix) < 128u;
            bool vx1 = ((unsigned)(ix + 1)) < 128u;
            float w00 = (1.f - wy) * (1.f - wx) * m;
            float w01 = (1.f - wy) * wx * m;
            float w10 = wy * (1.f - wx) * m;
            float w11 = wy * wx * m;
            if (!(vy0 && vx0)) w00 = 0.f;
            if (!(vy0 && vx1)) w01 = 0.f;
            if (!(vy1 && vx0)) w10 = 0.f;
            if (!(vy1 && vx1)) w11 = 0.f;
            s_tabw[k * 256 + tid] = make_float4(w00, w01, w10, w11);
            unsigned short xA = (unsigned short)min(max(ix, 0), 127);
            unsigned short xB = (unsigned short)min(max(ix + 1, 0), 127);
            unsigned short yA = (unsigned short)(min(max(iy, 0), 127) * 128);
            unsigned short yB = (unsigned short)(min(max(iy + 1, 0), 127) * 128);
            s_tabi[k * 256 + tid] = make_ushort4(xA, xB, yA, yB);
        }
    }

    // ---- weight chunk loader: chunk c covers ck=0..35 (ci*9+k), contiguous
    // 36 floats per oc at wgt[oc*576 + c*36]. Coalesced float4 LDG + STS.
    const float4* wsrc = (const float4*)wgt;
#define LOAD_W(c, buf)                                                        \
    {                                                                         \
        float* dst = s_w + (buf) * 2304;                                      \
        _Pragma("unroll")                                                     \
        for (int i = 0; i < 3; i++) {                                         \
            int idx4 = i * 256 + tid;                                         \
            if (idx4 < 576) {                                                 \
                int oc  = idx4 / 9;                                           \
                int ck4 = idx4 - oc * 9;                                      \
                float4 w4 = __ldg(&wsrc[oc * 144 + (c) * 9 + ck4]);           \
                int ck = ck4 * 4;                                             \
                dst[(ck + 0) * 64 + oc] = w4.x;                               \
                dst[(ck + 1) * 64 + oc] = w4.y;                               \
                dst[(ck + 2) * 64 + oc] = w4.z;                               \
                dst[(ck + 3) * 64 + oc] = w4.w;                               \
            }                                                                 \
        }                                                                     \
    }

    float acc[64];
#pragma unroll
    for (int o = 0; o < 64; o++) acc[o] = 0.f;

    LOAD_W(0, 0);
    __syncthreads();   // tabs + weight buf0 visible

    const float* xbase = xin + (size_t)b * 64 * HWSZ;

#pragma unroll 1
    for (int cc = 0; cc < 16; cc++) {
        const int cur = cc & 1;
        if (cc + 1 < 16) LOAD_W(cc + 1, cur ^ 1);   // overlaps gather+GEMM below

        // ---- gather 36 samples into registers (own pixel's tab)
        float samp[36];
        const float* xb = xbase + (size_t)cc * 4 * HWSZ;
#pragma unroll
        for (int k = 0; k < 9; k++) {
            float4  w4 = s_tabw[k * 256 + tid];
            ushort4 t  = s_tabi[k * 256 + tid];
            int iA = (int)t.z + (int)t.x;
            int iB = (int)t.z + (int)t.y;
            int iC = (int)t.w + (int)t.x;
            int iD = (int)t.w + (int)t.y;
#pragma unroll
            for (int ci = 0; ci < 4; ci++) {
                const float* p = xb + ci * HWSZ;
                samp[ci * 9 + k] = w4.x * __ldg(p + iA) + w4.y * __ldg(p + iB)
                                 + w4.z * __ldg(p + iC) + w4.w * __ldg(p + iD);
            }
        }

        // ---- GEMM: 36 ck, 64 oc, weights via warp-broadcast LDS.128
        const float* wb = s_w + cur * 2304;
#pragma unroll 4
        for (int ck = 0; ck < 36; ck++) {
            float sv = samp[ck];
            const float4* wr = (const float4*)(wb + ck * 64);
#pragma unroll
            for (int o4 = 0; o4 < 16; o4++) {
                float4 w4 = wr[o4];
                acc[o4 * 4 + 0] = fmaf(sv, w4.x, acc[o4 * 4 + 0]);
                acc[o4 * 4 + 1] = fmaf(sv, w4.y, acc[o4 * 4 + 1]);
                acc[o4 * 4 + 2] = fmaf(sv, w4.z, acc[o4 * 4 + 2]);
                acc[o4 * 4 + 3] = fmaf(sv, w4.w, acc[o4 * 4 + 3]);
            }
        }
        __syncthreads();   // buf(cur^1) ready for next iter; cur safe to refill
    }
#undef LOAD_W

    // ---- epilogue: bias + lrelu; per-oc stores are warp-coalesced (x = lanes)
    float* obase = out + (((size_t)b * 64) * HH + y) * WW + lx;
#pragma unroll
    for (int o = 0; o < 64; o++) {
        float v = acc[o] + __ldg(&bias[o]);
        v = (v >= 0.f) ? v : 0.1f * v;
        obase[(size_t)o * HWSZ] = v;
    }
}

extern "C" void kernel_launch(void* const* d_in, const int* in_sizes, int n_in,
                              void* d_out, int out_size)
{
    const float* nbr   = (const float*)d_in[0];
    const float* ref   = (const float*)d_in[1];
    const float* w1    = (const float*)d_in[2];
    const float* b1    = (const float*)d_in[3];
    const float* w2    = (const float*)d_in[4];
    const float* b2    = (const float*)d_in[5];
    const float* w3    = (const float*)d_in[6];
    const float* b3    = (const float*)d_in[7];
    const float* w_off = (const float*)d_in[8];
    const float* b_off = (const float*)d_in[9];
    const float* w_dcn = (const float*)d_in[10];
    const float* b_dcn = (const float*)d_in[11];

    float* out  = (float*)d_out;
    float* feat = out;                              // [B,64,H,W]
    float* offp = out + (size_t)BB * 64 * HWSZ;     // [B,18,H,W]
    float* mskp = offp + (size_t)BB * 18 * HWSZ;    // [B,9,H,W]

    float *bufA = nullptr, *bufB = nullptr;
    cudaGetSymbolAddress((void**)&bufA, g_bufA);
    cudaGetSymbolAddress((void**)&bufB, g_bufB);

    const int dcn_smem = 73728;
    cudaFuncSetAttribute(dcn_reg_k, cudaFuncAttributeMaxDynamicSharedMemorySize, dcn_smem);

    sched_warm_k<<<1, 32>>>();

    dim3 cblk(8, 16);
    // conv1: concat(nbr, ref) 128 -> 64, lrelu
    conv3x3_k<<<dim3(4, 8, BB * 8), cblk>>>(nbr, ref, 128, w1, b1, bufA, 64, 0, nullptr, nullptr);
    // conv2: 64 -> 64, lrelu
    conv3x3_k<<<dim3(4, 8, BB * 8), cblk>>>(bufA, nullptr, 64, w2, b2, bufB, 64, 0, nullptr, nullptr);
    // conv3: 64 -> 64, lrelu
    conv3x3_k<<<dim3(4, 8, BB * 8), cblk>>>(bufB, nullptr, 64, w3, b3, bufA, 64, 0, nullptr, nullptr);
    // conv_off: 64 -> 27, offsets (15*tanh) + mask (sigmoid), to d_out
    conv3x3_k<<<dim3(4, 8, BB * 4), cblk>>>(bufA, nullptr, 64, w_off, b_off, nullptr, 27, 1, offp, mskp);
    // DCNv2 (all-register) on nbr with offsets/mask from d_out, lrelu -> feat
    dcn_reg_k<<<dim3(HH / 2, BB), 256, dcn_smem>>>(nbr, offp, mskp, w_dcn, b_dcn, feat);
}